// round 7
// baseline (speedup 1.0000x reference)
#include <cuda_runtime.h>
#include <math.h>

#define NLAYERS 4
#define HID 64
#define NROWS 8192            // B*N = 2*4096
#define NPB   4096.0f         // rows per batch
#define TROWS 32              // rows per CTA tile
#define NBLK  256             // 8192 / 32
#define HTS 33                // ht[j][r] stride (conflict-free transpose store + lane read)
#define HSS 68                // hs[r][l] stride (float4-friendly, conflict-free lane reads)

// Scratch (no allocations allowed)
__device__ float g_h[NROWS * HID];
__device__ float g_S[NLAYERS * 2 * HID * HID];   // per layer, per batch: h^T h
__device__ float g_sv[NLAYERS * 2 * HID];        // per layer, per batch: colsum(h)
__device__ float g_Weff[2 * HID * HID];          // per batch effective weight
__device__ float g_beff[2 * HID];                // per batch effective bias

__device__ __forceinline__ float gelu_exact(float x) {
    return 0.5f * x * (1.0f + erff(x * 0.70710678118654752440f));
}

// ---------------------------------------------------------------------------
// S-phase (block 128): given tile hs[r][l] (stride HSS, r<32), accumulate
// S += hs^T hs and sv += colsum(hs). Thread: j in {lane, lane+32}, l-block of
// 16 per warp (broadcast reads).
// ---------------------------------------------------------------------------
__device__ __forceinline__ void accum_S(const float* hs, float* Sdst, float* svdst, int tid)
{
    int lane = tid & 31, wid = tid >> 5;
    int l0 = wid * 16;

    float s0[16], s1[16];
    #pragma unroll
    for (int b = 0; b < 16; b++) { s0[b] = 0.0f; s1[b] = 0.0f; }

    #pragma unroll 4
    for (int r = 0; r < TROWS; r++) {
        const float* hr = hs + r * HSS;
        float hj0 = hr[lane];
        float hj1 = hr[lane + 32];
        float4 b0 = *(const float4*)(hr + l0);
        float4 b1 = *(const float4*)(hr + l0 + 4);
        float4 b2 = *(const float4*)(hr + l0 + 8);
        float4 b3 = *(const float4*)(hr + l0 + 12);
        float bv[16] = {b0.x,b0.y,b0.z,b0.w, b1.x,b1.y,b1.z,b1.w,
                        b2.x,b2.y,b2.z,b2.w, b3.x,b3.y,b3.z,b3.w};
        #pragma unroll
        for (int b = 0; b < 16; b++) {
            s0[b] = fmaf(hj0, bv[b], s0[b]);
            s1[b] = fmaf(hj1, bv[b], s1[b]);
        }
    }
    float* d0 = Sdst + lane * HID + l0;
    float* d1 = Sdst + (lane + 32) * HID + l0;
    #pragma unroll
    for (int b = 0; b < 16; b++) {
        atomicAdd(d0 + b, s0[b]);
        atomicAdd(d1 + b, s1[b]);
    }
    if (tid < 64) {
        float s = 0.0f;
        #pragma unroll 8
        for (int r = 0; r < TROWS; r++) s += hs[r * HSS + tid];
        atomicAdd(&svdst[tid], s);
    }
}

// ---------------------------------------------------------------------------
// zero: clear S / sv accumulators (must run first each replay).
// ---------------------------------------------------------------------------
__global__ __launch_bounds__(256) void zero_kernel()
{
    int idx = blockIdx.x * 256 + threadIdx.x;
    if (idx < NLAYERS * 2 * HID * HID) g_S[idx] = 0.0f;
    if (idx < NLAYERS * 2 * HID)       g_sv[idx] = 0.0f;
}

// ---------------------------------------------------------------------------
// lift_S: h = x @ lift_w + lift_b; write g_h; accumulate S0, s0.
// grid 256 x 128.
// ---------------------------------------------------------------------------
__global__ __launch_bounds__(128) void lift_S_kernel(
    const float* __restrict__ x, const float* __restrict__ lw,
    const float* __restrict__ lb)
{
    __shared__ float hs[TROWS * HSS];
    int tid = threadIdx.x;
    int r0  = blockIdx.x * TROWS;
    int batch = r0 >> 12;

    #pragma unroll
    for (int it = 0; it < 16; it++) {
        int idx = tid + 128 * it;              // 2048 elements
        int r = idx >> 6, c = idx & 63;
        const float* xr = x + (r0 + r) * 3;
        float acc = lb[c];
        acc = fmaf(xr[0], lw[c],        acc);
        acc = fmaf(xr[1], lw[64 + c],   acc);
        acc = fmaf(xr[2], lw[128 + c],  acc);
        g_h[(r0 + r) * HID + c] = acc;
        hs[r * HSS + c] = acc;
    }
    __syncthreads();
    accum_S(hs, g_S + batch * (HID * HID), g_sv + batch * HID, tid);
}

// ---------------------------------------------------------------------------
// tiny_eff: per (batch, 8-col chunk): W_eff[:,l] = Wb[:,l] + c*Wq*M[:,l],
// M[:,l] = Wk^T (S Wv[:,l]) + w*bv[l] + bk*(u[l] + N*bv[l]),
// w = Wk^T s, u[l] = s . Wv[:,l].  b_eff[l] = bb[l] + c*bq.M[:,l].
// grid 16 x 256, dynamic smem.
// ---------------------------------------------------------------------------
__global__ __launch_bounds__(256) void tiny_eff_kernel(
    const float* __restrict__ qw, const float* __restrict__ qb,
    const float* __restrict__ kw, const float* __restrict__ kb,
    const float* __restrict__ vw, const float* __restrict__ vb,
    const float* __restrict__ bw, const float* __restrict__ bb,
    int layer)
{
    extern __shared__ float smT[];
    float* sS   = smT;               // [64][65]
    float* sWk  = sS  + 64 * 65;     // [64][65]
    float* sWq  = sWk + 64 * 65;     // [64][65]
    float* sWv8 = sWq + 64 * 65;     // [64][8]
    float* sA   = sWv8 + 64 * 8;     // [64][9]
    float* sM   = sA  + 64 * 9;      // [64][9]
    float* ssum = sM  + 64 * 9;      // [64]
    float* swv  = ssum + 64;         // [64]  w = Wk^T s
    float* su   = swv + 64;          // [8]

    int tid = threadIdx.x;
    int b   = blockIdx.x >> 3;
    int cc  = blockIdx.x & 7;
    int l0  = 8 * cc;

    const float* Sg = g_S + (layer * 2 + b) * (HID * HID);
    const float* sv = g_sv + (layer * 2 + b) * HID;

    #pragma unroll
    for (int it = 0; it < 16; it++) {
        int f = tid + 256 * it;                 // 4096 elems each
        int rr = f >> 6, mm = f & 63;
        sS [rr * 65 + mm] = Sg[f];
        sWk[rr * 65 + mm] = kw[f];
        sWq[rr * 65 + mm] = qw[f];
    }
    if (tid < 128) {
        int m = tid >> 1, hf = tid & 1;
        float4 v = *(const float4*)(vw + m * 64 + l0 + 4 * hf);
        *(float4*)(sWv8 + m * 8 + 4 * hf) = v;
    }
    if (tid < 64) ssum[tid] = sv[tid];
    __syncthreads();

    int j = tid & 63, g = tid >> 6;
    int ll = 2 * g;                              // this thread's 2 local l's
    int la = l0 + ll;

    // w[j] (group 0) and u[l] (group 1)
    if (g == 0) {
        float acc = 0.0f;
        #pragma unroll 8
        for (int m = 0; m < 64; m++) acc = fmaf(sWk[m * 65 + j], ssum[m], acc);
        swv[j] = acc;
    } else if (g == 1 && j < 8) {
        float acc = 0.0f;
        #pragma unroll 8
        for (int m = 0; m < 64; m++) acc = fmaf(ssum[m], sWv8[m * 8 + j], acc);
        su[j] = acc;
    }

    // A[:,l] = S Wv[:,l]  (all threads)
    {
        float a0 = 0.0f, a1 = 0.0f;
        #pragma unroll 8
        for (int m = 0; m < 64; m++) {
            float s = sS[j * 65 + m];
            a0 = fmaf(s, sWv8[m * 8 + ll],     a0);
            a1 = fmaf(s, sWv8[m * 8 + ll + 1], a1);
        }
        sA[j * 9 + ll]     = a0;
        sA[j * 9 + ll + 1] = a1;
    }
    __syncthreads();

    // M[:,l]
    {
        float bkj = kb[j];
        float bv0 = vb[la], bv1 = vb[la + 1];
        float m0 = fmaf(swv[j], bv0, bkj * (su[ll]     + NPB * bv0));
        float m1 = fmaf(swv[j], bv1, bkj * (su[ll + 1] + NPB * bv1));
        #pragma unroll 8
        for (int m = 0; m < 64; m++) {
            float wk = sWk[m * 65 + j];
            m0 = fmaf(wk, sA[m * 9 + ll],     m0);
            m1 = fmaf(wk, sA[m * 9 + ll + 1], m1);
        }
        sM[j * 9 + ll]     = m0;
        sM[j * 9 + ll + 1] = m1;
    }
    __syncthreads();

    // W_eff[:,l] and b_eff[l]
    const float cM = 0.125f / 4096.0f;
    {
        float e0 = 0.0f, e1 = 0.0f;
        #pragma unroll 8
        for (int m = 0; m < 64; m++) {
            float wq = sWq[j * 65 + m];
            e0 = fmaf(wq, sM[m * 9 + ll],     e0);
            e1 = fmaf(wq, sM[m * 9 + ll + 1], e1);
        }
        g_Weff[b * 4096 + j * 64 + la]     = fmaf(cM, e0, bw[j * 64 + la]);
        g_Weff[b * 4096 + j * 64 + la + 1] = fmaf(cM, e1, bw[j * 64 + la + 1]);
    }
    if (g == 2 && j < 8) {
        int l = l0 + j;
        float acc = 0.0f;
        #pragma unroll 8
        for (int j2 = 0; j2 < 64; j2++) acc = fmaf(qb[j2], sM[j2 * 9 + j], acc);
        g_beff[b * 64 + l] = fmaf(cM, acc, bb[l]);
    }
}

// ---------------------------------------------------------------------------
// apply_S (block 128, grid 256): h = gelu(h @ W_eff + b_eff) on a 32-row tile;
// if do_S, accumulate next-layer S, sv.
// GEMM layout: lane = row (32), warp = 16-col block (broadcast weight reads).
// ---------------------------------------------------------------------------
__global__ __launch_bounds__(128) void apply_S_kernel(int s_slot, int do_S)
{
    __shared__ float ht[64 * HTS];     // transposed h [j][r], r<32
    __shared__ float sw[64 * 64];      // W_eff [j][l]
    __shared__ float hs[TROWS * HSS];  // gelu'd tile [r][l]

    int tid  = threadIdx.x;
    int lane = tid & 31;
    int wid  = tid >> 5;
    int r0   = blockIdx.x * TROWS;
    int batch = r0 >> 12;

    // load h tile transposed: conflict-free (stride 33)
    #pragma unroll
    for (int it = 0; it < 16; it++) {
        int idx = tid + 128 * it;              // 2048 elements
        int r = idx >> 6, j = idx & 63;
        ht[j * HTS + r] = g_h[(r0 + r) * HID + j];
    }
    // load W_eff
    #pragma unroll
    for (int it = 0; it < 8; it++) {
        int f = tid + 128 * it;                // 1024 float4s
        *(float4*)(sw + 4 * f) = *(const float4*)(g_Weff + batch * 4096 + 4 * f);
    }
    __syncthreads();

    // GEMM: thread = (row=lane, 16 cols at l0)
    int l0 = wid * 16;
    float acc[16];
    #pragma unroll
    for (int b = 0; b < 16; b++) acc[b] = 0.0f;

    #pragma unroll 4
    for (int j = 0; j < 64; j++) {
        float hv = ht[j * HTS + lane];
        const float* wr = sw + j * 64 + l0;
        float4 w0 = *(const float4*)(wr);
        float4 w1 = *(const float4*)(wr + 4);
        float4 w2 = *(const float4*)(wr + 8);
        float4 w3 = *(const float4*)(wr + 12);
        float wv[16] = {w0.x,w0.y,w0.z,w0.w, w1.x,w1.y,w1.z,w1.w,
                        w2.x,w2.y,w2.z,w2.w, w3.x,w3.y,w3.z,w3.w};
        #pragma unroll
        for (int b = 0; b < 16; b++) acc[b] = fmaf(hv, wv[b], acc[b]);
    }

    // bias + gelu, stage into hs
    {
        const float* bp = g_beff + batch * 64 + l0;
        float* dst = hs + lane * HSS + l0;
        #pragma unroll
        for (int b4 = 0; b4 < 4; b4++) {
            float4 be = *(const float4*)(bp + 4 * b4);
            float4 o;
            o.x = gelu_exact(acc[4 * b4 + 0] + be.x);
            o.y = gelu_exact(acc[4 * b4 + 1] + be.y);
            o.z = gelu_exact(acc[4 * b4 + 2] + be.z);
            o.w = gelu_exact(acc[4 * b4 + 3] + be.w);
            *(float4*)(dst + 4 * b4) = o;
        }
    }
    __syncthreads();

    // coalesced write-back of gelu'd tile: 32 rows x 16 float4 = 512 float4s
    #pragma unroll
    for (int it = 0; it < 4; it++) {
        int f = tid + 128 * it;                // 512 float4s: r = f>>4, j4 = f&15
        int r = f >> 4, j4 = f & 15;
        *(float4*)(g_h + (r0 + r) * HID + 4 * j4) =
            *(const float4*)(hs + r * HSS + 4 * j4);
    }

    if (do_S) {
        accum_S(hs, g_S + (s_slot * 2 + batch) * (HID * HID),
                g_sv + (s_slot * 2 + batch) * HID, tid);
    }
}

// ---------------------------------------------------------------------------
// proj: out[row] = dot(h[row], proj_w) + proj_b. Warp per row.
// ---------------------------------------------------------------------------
__global__ __launch_bounds__(256) void proj_kernel(
    const float* __restrict__ pw, const float* __restrict__ pb,
    float* __restrict__ out)
{
    int tid = threadIdx.x;
    int lane = tid & 31, w = tid >> 5;
    int row = blockIdx.x * 8 + w;
    const float* hr = g_h + row * HID;
    float s = fmaf(hr[lane], pw[lane], hr[lane + 32] * pw[lane + 32]);
    #pragma unroll
    for (int o = 16; o; o >>= 1) s += __shfl_xor_sync(0xffffffffu, s, o);
    if (lane == 0) out[row] = s + pb[0];
}

// ---------------------------------------------------------------------------
extern "C" void kernel_launch(void* const* d_in, const int* in_sizes, int n_in,
                              void* d_out, int out_size)
{
    const float* x      = (const float*)d_in[0];
    const float* lift_w = (const float*)d_in[1];
    const float* lift_b = (const float*)d_in[2];
    const float* blk_w  = (const float*)d_in[3];
    const float* blk_b  = (const float*)d_in[4];
    const float* q_w    = (const float*)d_in[5];
    const float* q_b    = (const float*)d_in[6];
    const float* k_w    = (const float*)d_in[7];
    const float* k_b    = (const float*)d_in[8];
    const float* v_w    = (const float*)d_in[9];
    const float* v_b    = (const float*)d_in[10];
    const float* proj_w = (const float*)d_in[11];
    const float* proj_b = (const float*)d_in[12];
    float* out = (float*)d_out;

    const int smemT = (3 * 64 * 65 + 64 * 8 + 2 * 64 * 9 + 64 + 64 + 8) * 4;  // ~57 KB
    cudaFuncSetAttribute(tiny_eff_kernel,
                         cudaFuncAttributeMaxDynamicSharedMemorySize, smemT);

    zero_kernel<<<128, 256>>>();
    lift_S_kernel<<<NBLK, 128>>>(x, lift_w, lift_b);

    for (int i = 0; i < NLAYERS; i++) {
        tiny_eff_kernel<<<16, 256, smemT>>>(
            q_w + i * 4096, q_b + i * 64,
            k_w + i * 4096, k_b + i * 64,
            v_w + i * 4096, v_b + i * 64,
            blk_w + i * 4096, blk_b + i * 64,
            i);
        apply_S_kernel<<<NBLK, 128>>>(i + 1, (i < NLAYERS - 1) ? 1 : 0);
    }

    proj_kernel<<<1024, 256>>>(proj_w, proj_b, out);
}

// round 9
// speedup vs baseline: 1.5325x; 1.5325x over previous
#include <cuda_runtime.h>
#include <math.h>

#define NLAYERS 4
#define HID 64
#define NROWS 8192
#define NPB   4096.0f
#define TROWS 64
#define NCTA  128             // 8192/64; all co-resident (< 148 SMs)
#define NTHR  512
#define HSS   68              // hs[r][c] stride

// Scratch (no allocations allowed)
__device__ float g_S[NLAYERS * 2 * HID * HID];
__device__ float g_sv[NLAYERS * 2 * HID];
__device__ float g_Weff[2 * HID * HID];
__device__ float g_beff[2 * HID];
__device__ unsigned g_bar;    // zero-init at load; monotonic across replays

__device__ __forceinline__ float gelu_exact(float x) {
    return 0.5f * x * (1.0f + erff(x * 0.70710678118654752440f));
}

// Monotonic grid barrier: arrivals counted forever; goal = next multiple of 128.
__device__ __forceinline__ void grid_barrier() {
    __syncthreads();
    if (threadIdx.x == 0) {
        __threadfence();
        unsigned old = atomicAdd(&g_bar, 1u);
        unsigned goal = (old - (old & (NCTA - 1u))) + NCTA;
        unsigned cur;
        do {
            asm volatile("ld.global.acquire.gpu.u32 %0, [%1];"
                         : "=r"(cur) : "l"(&g_bar));
            if ((int)(cur - goal) >= 0) break;
            __nanosleep(64);
        } while (true);
    }
    __syncthreads();
}

// ---------------------------------------------------------------------------
// S-phase: S += hs^T hs, sv += colsum(hs). 512 threads, 64 rows.
// thread: 2 j's (2*tyj), 4 l's (4*txl).
// ---------------------------------------------------------------------------
__device__ __forceinline__ void accum_S(const float* hs, float* Sdst, float* svdst)
{
    int tid = threadIdx.x;
    int txl = tid & 15, tyj = tid >> 4;      // tyj 0..31
    float acc[2][4];
    #pragma unroll
    for (int a = 0; a < 2; a++)
        #pragma unroll
        for (int b = 0; b < 4; b++) acc[a][b] = 0.0f;

    const float* pj = hs + 2 * tyj;
    const float* pl = hs + 4 * txl;
    #pragma unroll 8
    for (int r = 0; r < TROWS; r++) {
        float2 kj = *(const float2*)(pj + r * HSS);
        float4 vl = *(const float4*)(pl + r * HSS);
        float va[4] = {vl.x, vl.y, vl.z, vl.w};
        #pragma unroll
        for (int b = 0; b < 4; b++) {
            acc[0][b] = fmaf(kj.x, va[b], acc[0][b]);
            acc[1][b] = fmaf(kj.y, va[b], acc[1][b]);
        }
    }
    #pragma unroll
    for (int a = 0; a < 2; a++) {
        float* dst = Sdst + (2 * tyj + a) * HID + 4 * txl;
        #pragma unroll
        for (int b = 0; b < 4; b++) atomicAdd(dst + b, acc[a][b]);
    }
    if (tid < 64) {
        float s = 0.0f;
        #pragma unroll 8
        for (int r = 0; r < TROWS; r++) s += hs[r * HSS + tid];
        atomicAdd(&svdst[tid], s);
    }
}

// ---------------------------------------------------------------------------
// tiny: CTAs 0..15 (b = cta>>3, 8-col chunk cc = cta&7) compute W_eff, b_eff.
// ---------------------------------------------------------------------------
__device__ void tiny_phase(float* r2, int layer, int cta,
    const float* qw, const float* qb, const float* kw, const float* kb,
    const float* vw, const float* vb, const float* bw, const float* bb)
{
    float* sS   = r2;                // [64][65]
    float* sWk  = sS  + 64 * 65;
    float* sWq  = sWk + 64 * 65;
    float* sWv8 = sWq + 64 * 65;     // [64][8]
    float* sA   = sWv8 + 64 * 8;     // [64][9]
    float* sM   = sA  + 64 * 9;      // [64][9]
    float* ssum = sM  + 64 * 9;      // [64]
    float* swv  = ssum + 64;         // [64]
    float* su   = swv + 64;          // [8]

    int tid = threadIdx.x;
    int b = cta >> 3, cc = cta & 7, l0 = 8 * cc;
    const float* Sg  = g_S  + (layer * 2 + b) * (HID * HID);
    const float* svg = g_sv + (layer * 2 + b) * HID;

    #pragma unroll
    for (int it = 0; it < 8; it++) {
        int f = tid + 512 * it;                 // 4096 elems each
        int rr = f >> 6, mm = f & 63;
        sS [rr * 65 + mm] = Sg[f];
        sWk[rr * 65 + mm] = kw[f];
        sWq[rr * 65 + mm] = qw[f];
    }
    if (tid < 128) {
        int m = tid >> 1, hf = tid & 1;
        float4 v = *(const float4*)(vw + m * 64 + l0 + 4 * hf);
        *(float4*)(sWv8 + m * 8 + 4 * hf) = v;
    }
    if (tid < 64) ssum[tid] = svg[tid];
    __syncthreads();

    int j = tid & 63, g = tid >> 6;             // g 0..7 (uniform per warp)
    int l = l0 + g;

    if (g == 0) {
        float a = 0.0f;
        #pragma unroll 8
        for (int m = 0; m < 64; m++) a = fmaf(sWk[m * 65 + j], ssum[m], a);
        swv[j] = a;
    } else if (g == 1 && j < 8) {
        float a = 0.0f;
        #pragma unroll 8
        for (int m = 0; m < 64; m++) a = fmaf(ssum[m], sWv8[m * 8 + j], a);
        su[j] = a;
    }
    {   // A[:,l] = S Wv[:,l]
        float a = 0.0f;
        #pragma unroll 8
        for (int m = 0; m < 64; m++) a = fmaf(sS[j * 65 + m], sWv8[m * 8 + g], a);
        sA[j * 9 + g] = a;
    }
    __syncthreads();
    {   // M[:,l]
        float bkj = kb[j], bvl = vb[l];
        float m0 = fmaf(swv[j], bvl, bkj * (su[g] + NPB * bvl));
        #pragma unroll 8
        for (int m = 0; m < 64; m++) m0 = fmaf(sWk[m * 65 + j], sA[m * 9 + g], m0);
        sM[j * 9 + g] = m0;
    }
    __syncthreads();
    const float cM = 0.125f / 4096.0f;
    {   // W_eff
        float e = 0.0f;
        #pragma unroll 8
        for (int m = 0; m < 64; m++) e = fmaf(sWq[j * 65 + m], sM[m * 9 + g], e);
        g_Weff[b * 4096 + j * 64 + l] = fmaf(cM, e, bw[j * 64 + l]);
    }
    if (g == 0 && j < 8) {
        int lb2 = l0 + j;
        float a = 0.0f;
        #pragma unroll 8
        for (int j2 = 0; j2 < 64; j2++) a = fmaf(qb[j2], sM[j2 * 9 + j], a);
        g_beff[b * 64 + lb2] = fmaf(cM, a, bb[lb2]);
    }
}

// ---------------------------------------------------------------------------
// apply: hs = gelu(hs @ W_eff + b_eff), in place. thread: rows {2ry,2ry+1},
// cols 4cg..4cg+3.
// ---------------------------------------------------------------------------
__device__ __forceinline__ void apply_phase(float* hs, float* r2, int batch)
{
    float* sw = r2;
    int tid = threadIdx.x;
    #pragma unroll
    for (int it = 0; it < 2; it++) {
        int f = tid + 512 * it;                 // 1024 float4s
        *(float4*)(sw + 4 * f) = *(const float4*)(g_Weff + batch * 4096 + 4 * f);
    }
    __syncthreads();

    int cg = tid & 15, ry = tid >> 4;           // ry 0..31
    float acc[2][4];
    #pragma unroll
    for (int a = 0; a < 2; a++)
        #pragma unroll
        for (int b = 0; b < 4; b++) acc[a][b] = 0.0f;

    const float* h0p = hs + (2 * ry) * HSS;
    const float* h1p = hs + (2 * ry + 1) * HSS;
    const float* wp  = sw + 4 * cg;
    #pragma unroll 8
    for (int j = 0; j < 64; j++) {
        float ha = h0p[j], hb = h1p[j];
        float4 wv = *(const float4*)(wp + j * 64);
        acc[0][0] = fmaf(ha, wv.x, acc[0][0]);
        acc[0][1] = fmaf(ha, wv.y, acc[0][1]);
        acc[0][2] = fmaf(ha, wv.z, acc[0][2]);
        acc[0][3] = fmaf(ha, wv.w, acc[0][3]);
        acc[1][0] = fmaf(hb, wv.x, acc[1][0]);
        acc[1][1] = fmaf(hb, wv.y, acc[1][1]);
        acc[1][2] = fmaf(hb, wv.z, acc[1][2]);
        acc[1][3] = fmaf(hb, wv.w, acc[1][3]);
    }

    float4 be = *(const float4*)(g_beff + batch * 64 + 4 * cg);
    float4 o0, o1;
    o0.x = gelu_exact(acc[0][0] + be.x);
    o0.y = gelu_exact(acc[0][1] + be.y);
    o0.z = gelu_exact(acc[0][2] + be.z);
    o0.w = gelu_exact(acc[0][3] + be.w);
    o1.x = gelu_exact(acc[1][0] + be.x);
    o1.y = gelu_exact(acc[1][1] + be.y);
    o1.z = gelu_exact(acc[1][2] + be.z);
    o1.w = gelu_exact(acc[1][3] + be.w);

    __syncthreads();                 // everyone done reading old hs
    *(float4*)(hs + (2 * ry) * HSS + 4 * cg)     = o0;
    *(float4*)(hs + (2 * ry + 1) * HSS + 4 * cg) = o1;
    __syncthreads();
}

// ---------------------------------------------------------------------------
__global__ __launch_bounds__(NTHR, 1) void fused_kernel(
    const float* __restrict__ x,  const float* __restrict__ lw,
    const float* __restrict__ lb, const float* __restrict__ blk_w,
    const float* __restrict__ blk_b,
    const float* __restrict__ q_w, const float* __restrict__ q_b,
    const float* __restrict__ k_w, const float* __restrict__ k_b,
    const float* __restrict__ v_w, const float* __restrict__ v_b,
    const float* __restrict__ pw,  const float* __restrict__ pb,
    float* __restrict__ out)
{
    extern __shared__ float smem[];
    float* hs = smem;                 // [64][HSS], resident all layers
    float* r2 = smem + TROWS * HSS;   // scratch: tiny arrays / W_eff

    int tid = threadIdx.x;
    int cta = blockIdx.x;
    int r0  = cta * TROWS;
    int batch = r0 >> 12;

    // zero S / sv accumulators (each replay)
    int zi = cta * NTHR + tid;
    if (zi < NLAYERS * 2 * HID * HID) g_S[zi] = 0.0f;
    if (zi < NLAYERS * 2 * HID)       g_sv[zi] = 0.0f;

    // lift into hs
    #pragma unroll
    for (int it = 0; it < 8; it++) {
        int idx = tid + 512 * it;              // 4096 elements
        int r = idx >> 6, c = idx & 63;
        const float* xr = x + (r0 + r) * 3;
        float a = lb[c];
        a = fmaf(xr[0], lw[c],       a);
        a = fmaf(xr[1], lw[64 + c],  a);
        a = fmaf(xr[2], lw[128 + c], a);
        hs[r * HSS + c] = a;
    }
    grid_barrier();                            // zeroing visible; hs synced
    accum_S(hs, g_S + batch * (HID * HID), g_sv + batch * HID);

    for (int layer = 0; layer < NLAYERS; layer++) {
        grid_barrier();                        // S_layer complete
        if (cta < 16)
            tiny_phase(r2, layer, cta,
                       q_w + layer * 4096, q_b + layer * 64,
                       k_w + layer * 4096, k_b + layer * 64,
                       v_w + layer * 4096, v_b + layer * 64,
                       blk_w + layer * 4096, blk_b + layer * 64);
        grid_barrier();                        // W_eff ready
        apply_phase(hs, r2, batch);
        if (layer < NLAYERS - 1)
            accum_S(hs, g_S + ((layer + 1) * 2 + batch) * (HID * HID),
                    g_sv + ((layer + 1) * 2 + batch) * HID);
    }

    // proj: 16 warps x 4 rows
    {
        int lane = tid & 31, w = tid >> 5;
        #pragma unroll
        for (int k = 0; k < 4; k++) {
            int row = w * 4 + k;
            const float* hr = hs + row * HSS;
            float s = fmaf(hr[lane], pw[lane], hr[lane + 32] * pw[lane + 32]);
            #pragma unroll
            for (int o = 16; o; o >>= 1) s += __shfl_xor_sync(0xffffffffu, s, o);
            if (lane == 0) out[r0 + row] = s + pb[0];
        }
    }
}

// ---------------------------------------------------------------------------
extern "C" void kernel_launch(void* const* d_in, const int* in_sizes, int n_in,
                              void* d_out, int out_size)
{
    const float* x      = (const float*)d_in[0];
    const float* lift_w = (const float*)d_in[1];
    const float* lift_b = (const float*)d_in[2];
    const float* blk_w  = (const float*)d_in[3];
    const float* blk_b  = (const float*)d_in[4];
    const float* q_w    = (const float*)d_in[5];
    const float* q_b    = (const float*)d_in[6];
    const float* k_w    = (const float*)d_in[7];
    const float* k_b    = (const float*)d_in[8];
    const float* v_w    = (const float*)d_in[9];
    const float* v_b    = (const float*)d_in[10];
    const float* proj_w = (const float*)d_in[11];
    const float* proj_b = (const float*)d_in[12];
    float* out = (float*)d_out;

    // smem: hs (64*HSS) + tiny scratch (3*64*65 + 64*8 + 2*64*9 + 64+64+8)
    const int smemB = (TROWS * HSS + 3 * 64 * 65 + 64 * 8 + 2 * 64 * 9 + 136) * 4;
    static int configured = 0;
    if (!configured) {
        cudaFuncSetAttribute(fused_kernel,
                             cudaFuncAttributeMaxDynamicSharedMemorySize, smemB);
        configured = 1;
    }

    fused_kernel<<<NCTA, NTHR, smemB>>>(
        x, lift_w, lift_b, blk_w, blk_b,
        q_w, q_b, k_w, k_b, v_w, v_b,
        proj_w, proj_b, out);
}

// round 11
// speedup vs baseline: 1.9762x; 1.2895x over previous
#include <cuda_runtime.h>
#include <math.h>

#define NLAYERS 4
#define HID 64
#define NROWS 8192            // B*N = 2*4096
#define NPB   4096.0f
#define TROWS 32              // rows per CTA tile
#define NBLK  256             // 8192 / 32 CTAs -> 2 CTAs/SM co-resident
#define HTS 34                // ht[j][r] stride: even (aligned float2), 2-way max conflict
#define HSS 68                // hs[r][l] stride

// Scratch (no allocations allowed)
__device__ float g_h[NROWS * HID];
__device__ float g_S[NLAYERS * 2 * HID * HID];   // per layer, per batch: h^T h
__device__ float g_sv[NLAYERS * 2 * HID];        // per layer, per batch: colsum(h)
__device__ float g_Weff[2 * HID * HID];
__device__ float g_beff[2 * HID];

__device__ __forceinline__ float gelu_exact(float x) {
    return 0.5f * x * (1.0f + erff(x * 0.70710678118654752440f));
}

__device__ __forceinline__ void red_v4(float* p, float a, float b, float c, float d) {
    asm volatile("red.global.add.v4.f32 [%0], {%1,%2,%3,%4};"
                 :: "l"(p), "f"(a), "f"(b), "f"(c), "f"(d) : "memory");
}

// ---------------------------------------------------------------------------
// S-phase (256 threads, 32-row tile): S += hs^T hs, sv += colsum(hs).
// thread: 4 j's (4*tyj), 4 l's (4*txl). Vector red for the 64x64 update.
// ---------------------------------------------------------------------------
__device__ __forceinline__ void accum_S(const float* hs, float* Sdst, float* svdst, int tid)
{
    int txl = tid & 15, tyj = tid >> 4;
    float macc[4][4];
    #pragma unroll
    for (int a = 0; a < 4; a++)
        #pragma unroll
        for (int b = 0; b < 4; b++) macc[a][b] = 0.0f;

    const float* pj = hs + 4 * tyj;
    const float* pl = hs + 4 * txl;
    #pragma unroll 8
    for (int r = 0; r < TROWS; r++) {
        float4 aj = *(const float4*)(pj + r * HSS);
        float4 bl = *(const float4*)(pl + r * HSS);
        float av[4] = {aj.x, aj.y, aj.z, aj.w};
        float bv[4] = {bl.x, bl.y, bl.z, bl.w};
        #pragma unroll
        for (int a = 0; a < 4; a++)
            #pragma unroll
            for (int b = 0; b < 4; b++)
                macc[a][b] = fmaf(av[a], bv[b], macc[a][b]);
    }
    #pragma unroll
    for (int a = 0; a < 4; a++)
        red_v4(Sdst + (4 * tyj + a) * HID + 4 * txl,
               macc[a][0], macc[a][1], macc[a][2], macc[a][3]);

    if (tid < 64) {
        float s = 0.0f;
        #pragma unroll 8
        for (int r = 0; r < TROWS; r++) s += hs[r * HSS + tid];
        atomicAdd(&svdst[tid], s);
    }
}

// ---------------------------------------------------------------------------
__global__ __launch_bounds__(256) void zero_kernel()
{
    int idx = blockIdx.x * 256 + threadIdx.x;
    if (idx < NLAYERS * 2 * HID * HID) g_S[idx] = 0.0f;
    if (idx < NLAYERS * 2 * HID)       g_sv[idx] = 0.0f;
}

// ---------------------------------------------------------------------------
// lift_S: h = x @ lift_w + lift_b; write g_h; accumulate S0, s0.
// grid 256 x 256.
// ---------------------------------------------------------------------------
__global__ __launch_bounds__(256) void lift_S_kernel(
    const float* __restrict__ x, const float* __restrict__ lw,
    const float* __restrict__ lb)
{
    __shared__ float hs[TROWS * HSS];
    int tid = threadIdx.x;
    int r0  = blockIdx.x * TROWS;
    int batch = r0 >> 12;

    #pragma unroll
    for (int it = 0; it < 8; it++) {
        int idx = tid + 256 * it;              // 2048 elements
        int r = idx >> 6, c = idx & 63;
        const float* xr = x + (r0 + r) * 3;
        float acc = lb[c];
        acc = fmaf(xr[0], lw[c],        acc);
        acc = fmaf(xr[1], lw[64 + c],   acc);
        acc = fmaf(xr[2], lw[128 + c],  acc);
        g_h[(r0 + r) * HID + c] = acc;
        hs[r * HSS + c] = acc;
    }
    __syncthreads();
    accum_S(hs, g_S + batch * (HID * HID), g_sv + batch * HID, tid);
}

// ---------------------------------------------------------------------------
// tiny_eff: per (batch, 8-col chunk) compute W_eff / b_eff. grid 16 x 256.
// (unchanged from the 80.6us version)
// ---------------------------------------------------------------------------
__global__ __launch_bounds__(256) void tiny_eff_kernel(
    const float* __restrict__ qw, const float* __restrict__ qb,
    const float* __restrict__ kw, const float* __restrict__ kb,
    const float* __restrict__ vw, const float* __restrict__ vb,
    const float* __restrict__ bw, const float* __restrict__ bb,
    int layer)
{
    extern __shared__ float smT[];
    float* sS   = smT;               // [64][65]
    float* sWk  = sS  + 64 * 65;
    float* sWq  = sWk + 64 * 65;
    float* sWv8 = sWq + 64 * 65;     // [64][8]
    float* sA   = sWv8 + 64 * 8;     // [64][9]
    float* sM   = sA  + 64 * 9;      // [64][9]
    float* ssum = sM  + 64 * 9;      // [64]
    float* swv  = ssum + 64;         // [64]
    float* su   = swv + 64;          // [8]

    int tid = threadIdx.x;
    int b   = blockIdx.x >> 3;
    int cc  = blockIdx.x & 7;
    int l0  = 8 * cc;

    const float* Sg = g_S + (layer * 2 + b) * (HID * HID);
    const float* sv = g_sv + (layer * 2 + b) * HID;

    #pragma unroll
    for (int it = 0; it < 16; it++) {
        int f = tid + 256 * it;
        int rr = f >> 6, mm = f & 63;
        sS [rr * 65 + mm] = Sg[f];
        sWk[rr * 65 + mm] = kw[f];
        sWq[rr * 65 + mm] = qw[f];
    }
    if (tid < 128) {
        int m = tid >> 1, hf = tid & 1;
        float4 v = *(const float4*)(vw + m * 64 + l0 + 4 * hf);
        *(float4*)(sWv8 + m * 8 + 4 * hf) = v;
    }
    if (tid < 64) ssum[tid] = sv[tid];
    __syncthreads();

    int j = tid & 63, g = tid >> 6;
    int ll = 2 * g;
    int la = l0 + ll;

    if (g == 0) {
        float acc = 0.0f;
        #pragma unroll 8
        for (int m = 0; m < 64; m++) acc = fmaf(sWk[m * 65 + j], ssum[m], acc);
        swv[j] = acc;
    } else if (g == 1 && j < 8) {
        float acc = 0.0f;
        #pragma unroll 8
        for (int m = 0; m < 64; m++) acc = fmaf(ssum[m], sWv8[m * 8 + j], acc);
        su[j] = acc;
    }

    {
        float a0 = 0.0f, a1 = 0.0f;
        #pragma unroll 8
        for (int m = 0; m < 64; m++) {
            float s = sS[j * 65 + m];
            a0 = fmaf(s, sWv8[m * 8 + ll],     a0);
            a1 = fmaf(s, sWv8[m * 8 + ll + 1], a1);
        }
        sA[j * 9 + ll]     = a0;
        sA[j * 9 + ll + 1] = a1;
    }
    __syncthreads();

    {
        float bkj = kb[j];
        float bv0 = vb[la], bv1 = vb[la + 1];
        float m0 = fmaf(swv[j], bv0, bkj * (su[ll]     + NPB * bv0));
        float m1 = fmaf(swv[j], bv1, bkj * (su[ll + 1] + NPB * bv1));
        #pragma unroll 8
        for (int m = 0; m < 64; m++) {
            float wk = sWk[m * 65 + j];
            m0 = fmaf(wk, sA[m * 9 + ll],     m0);
            m1 = fmaf(wk, sA[m * 9 + ll + 1], m1);
        }
        sM[j * 9 + ll]     = m0;
        sM[j * 9 + ll + 1] = m1;
    }
    __syncthreads();

    const float cM = 0.125f / 4096.0f;
    {
        float e0 = 0.0f, e1 = 0.0f;
        #pragma unroll 8
        for (int m = 0; m < 64; m++) {
            float wq = sWq[j * 65 + m];
            e0 = fmaf(wq, sM[m * 9 + ll],     e0);
            e1 = fmaf(wq, sM[m * 9 + ll + 1], e1);
        }
        g_Weff[b * 4096 + j * 64 + la]     = fmaf(cM, e0, bw[j * 64 + la]);
        g_Weff[b * 4096 + j * 64 + la + 1] = fmaf(cM, e1, bw[j * 64 + la + 1]);
    }
    if (g == 2 && j < 8) {
        int l = l0 + j;
        float acc = 0.0f;
        #pragma unroll 8
        for (int j2 = 0; j2 < 64; j2++) acc = fmaf(qb[j2], sM[j2 * 9 + j], acc);
        g_beff[b * 64 + l] = fmaf(cM, acc, bb[l]);
    }
}

// ---------------------------------------------------------------------------
// apply_S (grid 256, block 256, 32-row tile, 2 CTAs/SM):
// h = gelu(h @ W_eff + b_eff); if do_S accumulate next-layer S, sv.
// thread: rows {2rg, 2rg+1}, cols 4cg..4cg+3.
// ---------------------------------------------------------------------------
__global__ __launch_bounds__(256) void apply_S_kernel(int s_slot, int do_S)
{
    __shared__ float ht[64 * HTS];     // transposed h [j][r], r<32, even stride
    __shared__ float sw[64 * 64];      // W_eff [j][l]
    __shared__ float hs[TROWS * HSS];  // gelu'd tile [r][l]

    int tid  = threadIdx.x;
    int r0   = blockIdx.x * TROWS;
    int batch = r0 >> 12;

    // load h tile transposed
    #pragma unroll
    for (int it = 0; it < 8; it++) {
        int idx = tid + 256 * it;              // 2048 elements
        int r = idx >> 6, j = idx & 63;
        ht[j * HTS + r] = g_h[(r0 + r) * HID + j];
    }
    // load W_eff
    #pragma unroll
    for (int it = 0; it < 4; it++) {
        int f = tid + 256 * it;                // 1024 float4s
        *(float4*)(sw + 4 * f) = *(const float4*)(g_Weff + batch * 4096 + 4 * f);
    }
    __syncthreads();

    int cg = tid & 15, rg = tid >> 4;          // cols 4cg, rows {2rg, 2rg+1}
    float acc[2][4];
    #pragma unroll
    for (int a = 0; a < 2; a++)
        #pragma unroll
        for (int b = 0; b < 4; b++) acc[a][b] = 0.0f;

    const float* hp = ht + 2 * rg;
    const float* wp = sw + 4 * cg;
    #pragma unroll 8
    for (int j = 0; j < 64; j++) {
        float2 hv = *(const float2*)(hp + j * HTS);      // 2 rows (broadcast pair)
        float4 wv = *(const float4*)(wp + j * 64);
        acc[0][0] = fmaf(hv.x, wv.x, acc[0][0]);
        acc[0][1] = fmaf(hv.x, wv.y, acc[0][1]);
        acc[0][2] = fmaf(hv.x, wv.z, acc[0][2]);
        acc[0][3] = fmaf(hv.x, wv.w, acc[0][3]);
        acc[1][0] = fmaf(hv.y, wv.x, acc[1][0]);
        acc[1][1] = fmaf(hv.y, wv.y, acc[1][1]);
        acc[1][2] = fmaf(hv.y, wv.z, acc[1][2]);
        acc[1][3] = fmaf(hv.y, wv.w, acc[1][3]);
    }

    // bias + gelu, stage into hs
    {
        float4 be = *(const float4*)(g_beff + batch * 64 + 4 * cg);
        float bev[4] = {be.x, be.y, be.z, be.w};
        #pragma unroll
        for (int a = 0; a < 2; a++) {
            float4 o;
            o.x = gelu_exact(acc[a][0] + bev[0]);
            o.y = gelu_exact(acc[a][1] + bev[1]);
            o.z = gelu_exact(acc[a][2] + bev[2]);
            o.w = gelu_exact(acc[a][3] + bev[3]);
            *(float4*)(hs + (2 * rg + a) * HSS + 4 * cg) = o;
        }
    }
    __syncthreads();

    // coalesced write-back: 32 rows x 16 float4 = 512 float4s
    #pragma unroll
    for (int it = 0; it < 2; it++) {
        int f = tid + 256 * it;
        int r = f >> 4, j4 = f & 15;
        *(float4*)(g_h + (r0 + r) * HID + 4 * j4) =
            *(const float4*)(hs + r * HSS + 4 * j4);
    }

    if (do_S) {
        accum_S(hs, g_S + (s_slot * 2 + batch) * (HID * HID),
                g_sv + (s_slot * 2 + batch) * HID, tid);
    }
}

// ---------------------------------------------------------------------------
__global__ __launch_bounds__(256) void proj_kernel(
    const float* __restrict__ pw, const float* __restrict__ pb,
    float* __restrict__ out)
{
    int tid = threadIdx.x;
    int lane = tid & 31, w = tid >> 5;
    int row = blockIdx.x * 8 + w;
    const float* hr = g_h + row * HID;
    float s = fmaf(hr[lane], pw[lane], hr[lane + 32] * pw[lane + 32]);
    #pragma unroll
    for (int o = 16; o; o >>= 1) s += __shfl_xor_sync(0xffffffffu, s, o);
    if (lane == 0) out[row] = s + pb[0];
}

// ---------------------------------------------------------------------------
extern "C" void kernel_launch(void* const* d_in, const int* in_sizes, int n_in,
                              void* d_out, int out_size)
{
    const float* x      = (const float*)d_in[0];
    const float* lift_w = (const float*)d_in[1];
    const float* lift_b = (const float*)d_in[2];
    const float* blk_w  = (const float*)d_in[3];
    const float* blk_b  = (const float*)d_in[4];
    const float* q_w    = (const float*)d_in[5];
    const float* q_b    = (const float*)d_in[6];
    const float* k_w    = (const float*)d_in[7];
    const float* k_b    = (const float*)d_in[8];
    const float* v_w    = (const float*)d_in[9];
    const float* v_b    = (const float*)d_in[10];
    const float* proj_w = (const float*)d_in[11];
    const float* proj_b = (const float*)d_in[12];
    float* out = (float*)d_out;

    const int smemT = (3 * 64 * 65 + 64 * 8 + 2 * 64 * 9 + 64 + 64 + 8) * 4;  // ~57 KB
    cudaFuncSetAttribute(tiny_eff_kernel,
                         cudaFuncAttributeMaxDynamicSharedMemorySize, smemT);

    zero_kernel<<<128, 256>>>();
    lift_S_kernel<<<NBLK, 256>>>(x, lift_w, lift_b);

    for (int i = 0; i < NLAYERS; i++) {
        tiny_eff_kernel<<<16, 256, smemT>>>(
            q_w + i * 4096, q_b + i * 64,
            k_w + i * 4096, k_b + i * 64,
            v_w + i * 4096, v_b + i * 64,
            blk_w + i * 4096, blk_b + i * 64,
            i);
        apply_S_kernel<<<NBLK, 256>>>(i + 1, (i < NLAYERS - 1) ? 1 : 0);
    }

    proj_kernel<<<1024, 256>>>(proj_w, proj_b, out);
}

// round 16
// speedup vs baseline: 2.0468x; 1.0357x over previous
#include <cuda_runtime.h>
#include <math.h>

#define NLAYERS 4
#define HID 64
#define NROWS 8192            // B*N = 2*4096
#define NPB   4096.0f
#define TROWS 32              // rows per CTA tile
#define NBLK  256             // 8192 / 32 CTAs -> 2 CTAs/SM co-resident
#define HTS 36                // ht[j][r] stride: mult of 4 (aligned float4 reads)
#define HSS 68                // hs[r][l] stride

// Scratch (no allocations allowed)
__device__ float g_h[NROWS * HID];
__device__ float g_S[NLAYERS * 2 * HID * HID];   // per layer, per batch: h^T h
__device__ float g_sv[NLAYERS * 2 * HID];        // per layer, per batch: colsum(h)
__device__ float g_Weff[2 * HID * HID];
__device__ float g_beff[2 * HID];

__device__ __forceinline__ float gelu_exact(float x) {
    return 0.5f * x * (1.0f + erff(x * 0.70710678118654752440f));
}

__device__ __forceinline__ void red_v4(float* p, float a, float b, float c, float d) {
    asm volatile("red.global.add.v4.f32 [%0], {%1,%2,%3,%4};"
                 :: "l"(p), "f"(a), "f"(b), "f"(c), "f"(d) : "memory");
}

// ---------------------------------------------------------------------------
// S-phase (256 threads, 32-row tile): S += hs^T hs, sv += colsum(hs).
// thread: 4 j's (4*tyj), 4 l's (4*txl). Vector red for the 64x64 update.
// ---------------------------------------------------------------------------
__device__ __forceinline__ void accum_S(const float* hs, float* Sdst, float* svdst, int tid)
{
    int txl = tid & 15, tyj = tid >> 4;
    float macc[4][4];
    #pragma unroll
    for (int a = 0; a < 4; a++)
        #pragma unroll
        for (int b = 0; b < 4; b++) macc[a][b] = 0.0f;

    const float* pj = hs + 4 * tyj;
    const float* pl = hs + 4 * txl;
    #pragma unroll 8
    for (int r = 0; r < TROWS; r++) {
        float4 aj = *(const float4*)(pj + r * HSS);
        float4 bl = *(const float4*)(pl + r * HSS);
        float av[4] = {aj.x, aj.y, aj.z, aj.w};
        float bv[4] = {bl.x, bl.y, bl.z, bl.w};
        #pragma unroll
        for (int a = 0; a < 4; a++)
            #pragma unroll
            for (int b = 0; b < 4; b++)
                macc[a][b] = fmaf(av[a], bv[b], macc[a][b]);
    }
    #pragma unroll
    for (int a = 0; a < 4; a++)
        red_v4(Sdst + (4 * tyj + a) * HID + 4 * txl,
               macc[a][0], macc[a][1], macc[a][2], macc[a][3]);

    if (tid < 64) {
        float s = 0.0f;
        #pragma unroll 8
        for (int r = 0; r < TROWS; r++) s += hs[r * HSS + tid];
        atomicAdd(&svdst[tid], s);
    }
}

// ---------------------------------------------------------------------------
__global__ __launch_bounds__(256) void zero_kernel()
{
    int idx = blockIdx.x * 256 + threadIdx.x;
    if (idx < NLAYERS * 2 * HID * HID) g_S[idx] = 0.0f;
    if (idx < NLAYERS * 2 * HID)       g_sv[idx] = 0.0f;
}

// ---------------------------------------------------------------------------
// lift_S: h = x @ lift_w + lift_b; write g_h; accumulate S0, s0.
// grid 256 x 256.
// ---------------------------------------------------------------------------
__global__ __launch_bounds__(256) void lift_S_kernel(
    const float* __restrict__ x, const float* __restrict__ lw,
    const float* __restrict__ lb)
{
    __shared__ float hs[TROWS * HSS];
    int tid = threadIdx.x;
    int r0  = blockIdx.x * TROWS;
    int batch = r0 >> 12;

    #pragma unroll
    for (int it = 0; it < 8; it++) {
        int idx = tid + 256 * it;              // 2048 elements
        int r = idx >> 6, c = idx & 63;
        const float* xr = x + (r0 + r) * 3;
        float acc = lb[c];
        acc = fmaf(xr[0], lw[c],        acc);
        acc = fmaf(xr[1], lw[64 + c],   acc);
        acc = fmaf(xr[2], lw[128 + c],  acc);
        g_h[(r0 + r) * HID + c] = acc;
        hs[r * HSS + c] = acc;
    }
    __syncthreads();
    accum_S(hs, g_S + batch * (HID * HID), g_sv + batch * HID, tid);
}

// ---------------------------------------------------------------------------
// tiny_eff: per (batch, 8-col chunk) compute W_eff / b_eff. grid 16 x 256.
// ---------------------------------------------------------------------------
__global__ __launch_bounds__(256) void tiny_eff_kernel(
    const float* __restrict__ qw, const float* __restrict__ qb,
    const float* __restrict__ kw, const float* __restrict__ kb,
    const float* __restrict__ vw, const float* __restrict__ vb,
    const float* __restrict__ bw, const float* __restrict__ bb,
    int layer)
{
    extern __shared__ float smT[];
    float* sS   = smT;               // [64][65]
    float* sWk  = sS  + 64 * 65;
    float* sWq  = sWk + 64 * 65;
    float* sWv8 = sWq + 64 * 65;     // [64][8]
    float* sA   = sWv8 + 64 * 8;     // [64][9]
    float* sM   = sA  + 64 * 9;      // [64][9]
    float* ssum = sM  + 64 * 9;      // [64]
    float* swv  = ssum + 64;         // [64]
    float* su   = swv + 64;          // [8]

    int tid = threadIdx.x;
    int b   = blockIdx.x >> 3;
    int cc  = blockIdx.x & 7;
    int l0  = 8 * cc;

    const float* Sg = g_S + (layer * 2 + b) * (HID * HID);
    const float* sv = g_sv + (layer * 2 + b) * HID;

    #pragma unroll
    for (int it = 0; it < 16; it++) {
        int f = tid + 256 * it;
        int rr = f >> 6, mm = f & 63;
        sS [rr * 65 + mm] = Sg[f];
        sWk[rr * 65 + mm] = kw[f];
        sWq[rr * 65 + mm] = qw[f];
    }
    if (tid < 128) {
        int m = tid >> 1, hf = tid & 1;
        float4 v = *(const float4*)(vw + m * 64 + l0 + 4 * hf);
        *(float4*)(sWv8 + m * 8 + 4 * hf) = v;
    }
    if (tid < 64) ssum[tid] = sv[tid];
    __syncthreads();

    int j = tid & 63, g = tid >> 6;
    int ll = 2 * g;
    int la = l0 + ll;

    if (g == 0) {
        float acc = 0.0f;
        #pragma unroll 8
        for (int m = 0; m < 64; m++) acc = fmaf(sWk[m * 65 + j], ssum[m], acc);
        swv[j] = acc;
    } else if (g == 1 && j < 8) {
        float acc = 0.0f;
        #pragma unroll 8
        for (int m = 0; m < 64; m++) acc = fmaf(ssum[m], sWv8[m * 8 + j], acc);
        su[j] = acc;
    }

    {
        float a0 = 0.0f, a1 = 0.0f;
        #pragma unroll 8
        for (int m = 0; m < 64; m++) {
            float s = sS[j * 65 + m];
            a0 = fmaf(s, sWv8[m * 8 + ll],     a0);
            a1 = fmaf(s, sWv8[m * 8 + ll + 1], a1);
        }
        sA[j * 9 + ll]     = a0;
        sA[j * 9 + ll + 1] = a1;
    }
    __syncthreads();

    {
        float bkj = kb[j];
        float bv0 = vb[la], bv1 = vb[la + 1];
        float m0 = fmaf(swv[j], bv0, bkj * (su[ll]     + NPB * bv0));
        float m1 = fmaf(swv[j], bv1, bkj * (su[ll + 1] + NPB * bv1));
        #pragma unroll 8
        for (int m = 0; m < 64; m++) {
            float wk = sWk[m * 65 + j];
            m0 = fmaf(wk, sA[m * 9 + ll],     m0);
            m1 = fmaf(wk, sA[m * 9 + ll + 1], m1);
        }
        sM[j * 9 + ll]     = m0;
        sM[j * 9 + ll + 1] = m1;
    }
    __syncthreads();

    const float cM = 0.125f / 4096.0f;
    {
        float e0 = 0.0f, e1 = 0.0f;
        #pragma unroll 8
        for (int m = 0; m < 64; m++) {
            float wq = sWq[j * 65 + m];
            e0 = fmaf(wq, sM[m * 9 + ll],     e0);
            e1 = fmaf(wq, sM[m * 9 + ll + 1], e1);
        }
        g_Weff[b * 4096 + j * 64 + la]     = fmaf(cM, e0, bw[j * 64 + la]);
        g_Weff[b * 4096 + j * 64 + la + 1] = fmaf(cM, e1, bw[j * 64 + la + 1]);
    }
    if (g == 2 && j < 8) {
        int l = l0 + j;
        float acc = 0.0f;
        #pragma unroll 8
        for (int j2 = 0; j2 < 64; j2++) acc = fmaf(qb[j2], sM[j2 * 9 + j], acc);
        g_beff[b * 64 + l] = fmaf(cM, acc, bb[l]);
    }
}

// ---------------------------------------------------------------------------
// apply_S (grid 256, block 256, 32-row tile, 2 CTAs/SM), split-K 4x4 tiles:
// wg = tid>>7 accumulates j-range [32wg, 32wg+32) with a 4x4 register tile.
// Storer half writes partials to pbuf; finisher half combines + bias + gelu.
// mode 0: write g_h and accumulate next-layer S. mode 1 (last layer): proj
// directly from smem, no g_h write.
// ---------------------------------------------------------------------------
__global__ __launch_bounds__(256) void apply_S_kernel(
    int s_slot, int mode,
    const float* __restrict__ pw, const float* __restrict__ pb,
    float* __restrict__ out)
{
    __shared__ float ht[64 * HTS];       // transposed h [j][r]
    __shared__ float sw[64 * 64];        // W_eff [j][l]
    __shared__ float hs[TROWS * HSS];    // gelu'd tile [r][l]
    __shared__ float pbuf[TROWS * HSS];  // split-K partials

    int tid  = threadIdx.x;
    int r0   = blockIdx.x * TROWS;
    int batch = r0 >> 12;

    // load h tile transposed
    #pragma unroll
    for (int it = 0; it < 8; it++) {
        int idx = tid + 256 * it;              // 2048 elements
        int r = idx >> 6, j = idx & 63;
        ht[j * HTS + r] = g_h[(r0 + r) * HID + j];
    }
    // load W_eff
    #pragma unroll
    for (int it = 0; it < 4; it++) {
        int f = tid + 256 * it;                // 1024 float4s
        *(float4*)(sw + 4 * f) = *(const float4*)(g_Weff + batch * 4096 + 4 * f);
    }
    __syncthreads();

    int wg = tid >> 7;                  // j-half
    int t  = tid & 127;
    int cg = t & 15;                    // cols 4cg..4cg+3
    int rg = t >> 4;                    // rows 4rg..4rg+3
    float acc[4][4];
    #pragma unroll
    for (int a = 0; a < 4; a++)
        #pragma unroll
        for (int b = 0; b < 4; b++) acc[a][b] = 0.0f;

    const float* hp = ht + (32 * wg) * HTS + 4 * rg;
    const float* wp = sw + (32 * wg) * 64 + 4 * cg;
    #pragma unroll 8
    for (int jj = 0; jj < 32; jj++) {
        float4 hv = *(const float4*)(hp + jj * HTS);    // 4 rows (broadcast)
        float4 wv = *(const float4*)(wp + jj * 64);     // 4 cols
        float ha[4] = {hv.x, hv.y, hv.z, hv.w};
        #pragma unroll
        for (int a = 0; a < 4; a++) {
            acc[a][0] = fmaf(ha[a], wv.x, acc[a][0]);
            acc[a][1] = fmaf(ha[a], wv.y, acc[a][1]);
            acc[a][2] = fmaf(ha[a], wv.z, acc[a][2]);
            acc[a][3] = fmaf(ha[a], wv.w, acc[a][3]);
        }
    }

    // split epilogue: storer = (wg==0) == (rg>=4); finisher combines its rows
    int storer = (wg == 0) ? (rg >= 4) : (rg < 4);
    if (storer) {
        #pragma unroll
        for (int a = 0; a < 4; a++)
            *(float4*)(pbuf + (4 * rg + a) * HSS + 4 * cg) =
                make_float4(acc[a][0], acc[a][1], acc[a][2], acc[a][3]);
    }
    __syncthreads();
    if (!storer) {
        float4 be = *(const float4*)(g_beff + batch * 64 + 4 * cg);
        #pragma unroll
        for (int a = 0; a < 4; a++) {
            float4 p = *(const float4*)(pbuf + (4 * rg + a) * HSS + 4 * cg);
            float4 o;
            o.x = gelu_exact(acc[a][0] + p.x + be.x);
            o.y = gelu_exact(acc[a][1] + p.y + be.y);
            o.z = gelu_exact(acc[a][2] + p.z + be.z);
            o.w = gelu_exact(acc[a][3] + p.w + be.w);
            *(float4*)(hs + (4 * rg + a) * HSS + 4 * cg) = o;
        }
    }
    __syncthreads();

    if (mode == 0) {
        // coalesced write-back: 512 float4s
        #pragma unroll
        for (int it = 0; it < 2; it++) {
            int f = tid + 256 * it;
            int r = f >> 4, j4 = f & 15;
            *(float4*)(g_h + (r0 + r) * HID + 4 * j4) =
                *(const float4*)(hs + r * HSS + 4 * j4);
        }
        accum_S(hs, g_S + (s_slot * 2 + batch) * (HID * HID),
                g_sv + (s_slot * 2 + batch) * HID, tid);
    } else {
        // fused proj: 8 warps x 4 rows, dot(hs[row], pw) + pb
        int lane = tid & 31, w = tid >> 5;
        #pragma unroll
        for (int k = 0; k < 4; k++) {
            int row = w * 4 + k;
            const float* hr = hs + row * HSS;
            float s = fmaf(hr[lane], pw[lane], hr[lane + 32] * pw[lane + 32]);
            #pragma unroll
            for (int o = 16; o; o >>= 1) s += __shfl_xor_sync(0xffffffffu, s, o);
            if (lane == 0) out[r0 + row] = s + pb[0];
        }
    }
}

// ---------------------------------------------------------------------------
extern "C" void kernel_launch(void* const* d_in, const int* in_sizes, int n_in,
                              void* d_out, int out_size)
{
    const float* x      = (const float*)d_in[0];
    const float* lift_w = (const float*)d_in[1];
    const float* lift_b = (const float*)d_in[2];
    const float* blk_w  = (const float*)d_in[3];
    const float* blk_b  = (const float*)d_in[4];
    const float* q_w    = (const float*)d_in[5];
    const float* q_b    = (const float*)d_in[6];
    const float* k_w    = (const float*)d_in[7];
    const float* k_b    = (const float*)d_in[8];
    const float* v_w    = (const float*)d_in[9];
    const float* v_b    = (const float*)d_in[10];
    const float* proj_w = (const float*)d_in[11];
    const float* proj_b = (const float*)d_in[12];
    float* out = (float*)d_out;

    const int smemT = (3 * 64 * 65 + 64 * 8 + 2 * 64 * 9 + 64 + 64 + 8) * 4;  // ~57 KB
    cudaFuncSetAttribute(tiny_eff_kernel,
                         cudaFuncAttributeMaxDynamicSharedMemorySize, smemT);

    zero_kernel<<<128, 256>>>();
    lift_S_kernel<<<NBLK, 256>>>(x, lift_w, lift_b);

    for (int i = 0; i < NLAYERS; i++) {
        tiny_eff_kernel<<<16, 256, smemT>>>(
            q_w + i * 4096, q_b + i * 64,
            k_w + i * 4096, k_b + i * 64,
            v_w + i * 4096, v_b + i * 64,
            blk_w + i * 4096, blk_b + i * 64,
            i);
        apply_S_kernel<<<NBLK, 256>>>(i + 1, (i == NLAYERS - 1) ? 1 : 0,
                                      proj_w, proj_b, out);
    }
}